// round 13
// baseline (speedup 1.0000x reference)
#include <cuda_runtime.h>
#include <cstdint>

#define CH   256
#define IMG  128
#define HW   (IMG*IMG)
#define BATCH 4
#define HEADS 4

__device__ __forceinline__ float tf32r(float x) {
    uint32_t r; asm("cvt.rna.tf32.f32 %0, %1;" : "=r"(r) : "f"(x));
    return __uint_as_float(r);
}
__device__ __forceinline__ void mma8(float* d, uint32_t a0, uint32_t a1,
                                     uint32_t a2, uint32_t a3,
                                     uint32_t b0, uint32_t b1) {
    asm("mma.sync.aligned.m16n8k8.row.col.f32.tf32.tf32.f32 "
        "{%0,%1,%2,%3},{%4,%5,%6,%7},{%8,%9},{%0,%1,%2,%3};"
        : "+f"(d[0]), "+f"(d[1]), "+f"(d[2]), "+f"(d[3])
        : "r"(a0), "r"(a1), "r"(a2), "r"(a3), "r"(b0), "r"(b1));
}
__device__ __forceinline__ void mma16b(float* d, const uint32_t* a,
                                       uint32_t b0, uint32_t b1) {
    asm("mma.sync.aligned.m16n8k16.row.col.f32.bf16.bf16.f32 "
        "{%0,%1,%2,%3},{%4,%5,%6,%7},{%8,%9},{%0,%1,%2,%3};"
        : "+f"(d[0]), "+f"(d[1]), "+f"(d[2]), "+f"(d[3])
        : "r"(a[0]), "r"(a[1]), "r"(a[2]), "r"(a[3]), "r"(b0), "r"(b1));
}
__device__ __forceinline__ void bsplit2(float xe, float xo,
                                        uint32_t& hi, uint32_t& lo) {
    uint32_t h;
    asm("cvt.rn.bf16x2.f32 %0, %1, %2;" : "=r"(h) : "f"(xo), "f"(xe));
    float re = xe - __uint_as_float(h << 16);
    float ro = xo - __uint_as_float(h & 0xffff0000u);
    asm("cvt.rn.bf16x2.f32 %0, %1, %2;" : "=r"(lo) : "f"(ro), "f"(re));
    hi = h;
}

__device__ float g_naux[(long)BATCH*CH*HW];
__device__ float g_q   [(long)BATCH*HW*CH];
__device__ float g_k   [(long)BATCH*HW*CH];
__device__ float g_v   [(long)BATCH*HW*CH];
__device__ float g_wt  [512*256 + 3*256*256];

__global__ void transpose_w(const float* __restrict__ wm,
                            const float* __restrict__ wq,
                            const float* __restrict__ wk,
                            const float* __restrict__ wv,
                            float* __restrict__ wt)
{
    int t = blockIdx.x * 256 + threadIdx.x;
    if (t < 131072)      { int k = t >> 8, o = t & 255; wt[t] = wm[o * 512 + k]; }
    else if (t < 196608) { int u = t - 131072; wt[t] = wq[(u & 255) * 256 + (u >> 8)]; }
    else if (t < 262144) { int u = t - 196608; wt[t] = wk[(u & 255) * 256 + (u >> 8)]; }
    else if (t < 327680) { int u = t - 262144; wt[t] = wv[(u & 255) * 256 + (u >> 8)]; }
}

// ---------------------------------------------------------------------------
// Split-bf16 tensor-core conv GEMM — unchanged from R12 (validated).
// ---------------------------------------------------------------------------
__global__ __launch_bounds__(256, 2)
void gemm_b(const float* __restrict__ P,  long pB, int ldP,
            const float* __restrict__ Q0, const float* __restrict__ Q1,
            long qB, int ldQ, int K, int K0,
            float* __restrict__ C, int ldc,
            const float* __restrict__ bias, float scale, int mode, int mswap)
{
    const int tid  = threadIdx.x;
    const int lane = tid & 31, w = tid >> 5;
    const int gid  = lane >> 2, tig = lane & 3;
    const int b    = blockIdx.z;
    const int m0   = (mswap ? blockIdx.x : blockIdx.y) * 128;
    const int n0   = (mswap ? blockIdx.y : blockIdx.x) * 128;
    const float* Pb  = P  + (long)b * pB;
    const float* Q0b = Q0 + (long)b * qB;
    const float* Q1b = Q1 ? (Q1 + (long)b * qB) : nullptr;
    float* Cb = C + (long)b * CH * HW;

    __shared__ uint32_t PH[2][8][136], PL[2][8][136];
    __shared__ uint32_t QH[2][8][136], QL[2][8][136];

    const int side = tid >> 7;
    const int lt   = tid & 127;
    const int k2   = lt >> 4;
    const int mq   = (lt & 15) * 8;

    const int wm = w >> 2, wn = w & 3;
    float Cf[4][4][4];
#pragma unroll
    for (int mt = 0; mt < 4; mt++)
#pragma unroll
        for (int nt = 0; nt < 4; nt++)
#pragma unroll
            for (int q = 0; q < 4; q++) Cf[mt][nt][q] = 0.f;

    const int ntiles = K / 16;
    float4 e0, e1, o0, o1;

    auto loadT = [&](int kb) {
        int kr = kb + 2 * k2;
        if (side == 0) {
            const float* s0 = Pb + (long)kr * ldP + m0 + mq;
            const float* s1 = s0 + ldP;
            e0 = *(const float4*)&s0[0]; e1 = *(const float4*)&s0[4];
            o0 = *(const float4*)&s1[0]; o1 = *(const float4*)&s1[4];
        } else {
            const float* s0 = ((kr     < K0) ? (Q0b + (long)kr * ldQ)
                                             : (Q1b + (long)(kr - K0) * ldQ)) + n0 + mq;
            const float* s1 = ((kr + 1 < K0) ? (Q0b + (long)(kr + 1) * ldQ)
                                             : (Q1b + (long)(kr + 1 - K0) * ldQ)) + n0 + mq;
            e0 = *(const float4*)&s0[0]; e1 = *(const float4*)&s0[4];
            o0 = *(const float4*)&s1[0]; o1 = *(const float4*)&s1[4];
        }
    };
    auto storeT = [&](int buf) {
        float ev[8] = {e0.x,e0.y,e0.z,e0.w,e1.x,e1.y,e1.z,e1.w};
        float ov[8] = {o0.x,o0.y,o0.z,o0.w,o1.x,o1.y,o1.z,o1.w};
        uint32_t hs[8], ls[8];
#pragma unroll
        for (int m = 0; m < 8; m++) bsplit2(ev[m], ov[m], hs[m], ls[m]);
        uint32_t* H = side ? &QH[buf][k2][mq] : &PH[buf][k2][mq];
        uint32_t* L = side ? &QL[buf][k2][mq] : &PL[buf][k2][mq];
        *(uint4*)&H[0] = make_uint4(hs[0], hs[1], hs[2], hs[3]);
        *(uint4*)&H[4] = make_uint4(hs[4], hs[5], hs[6], hs[7]);
        *(uint4*)&L[0] = make_uint4(ls[0], ls[1], ls[2], ls[3]);
        *(uint4*)&L[4] = make_uint4(ls[4], ls[5], ls[6], ls[7]);
    };

    loadT(0); storeT(0);
    __syncthreads();

    for (int kt = 0; kt < ntiles; kt++) {
        const int cur = kt & 1, nxt = cur ^ 1;
        if (kt + 1 < ntiles) loadT((kt + 1) * 16);

        uint32_t bh[4][2], bl[4][2];
#pragma unroll
        for (int nt = 0; nt < 4; nt++) {
            int n = wn * 32 + nt * 8 + gid;
            bh[nt][0] = QH[cur][tig][n];     bh[nt][1] = QH[cur][tig + 4][n];
            bl[nt][0] = QL[cur][tig][n];     bl[nt][1] = QL[cur][tig + 4][n];
        }
#pragma unroll
        for (int mt = 0; mt < 4; mt++) {
            int m = wm * 64 + mt * 16 + gid;
            uint32_t ah[4] = {PH[cur][tig][m], PH[cur][tig][m + 8],
                              PH[cur][tig + 4][m], PH[cur][tig + 4][m + 8]};
            uint32_t al[4] = {PL[cur][tig][m], PL[cur][tig][m + 8],
                              PL[cur][tig + 4][m], PL[cur][tig + 4][m + 8]};
#pragma unroll
            for (int nt = 0; nt < 4; nt++) {
                mma16b(Cf[mt][nt], ah, bh[nt][0], bh[nt][1]);
                mma16b(Cf[mt][nt], ah, bl[nt][0], bl[nt][1]);
                mma16b(Cf[mt][nt], al, bh[nt][0], bh[nt][1]);
            }
        }
        if (kt + 1 < ntiles) { __syncthreads(); storeT(nxt); __syncthreads(); }
    }

#pragma unroll
    for (int mt = 0; mt < 4; mt++) {
        int r0 = m0 + wm * 64 + mt * 16 + gid;
        float bi0 = 0.f, bi1 = 0.f;
        if (mode == 0) { bi0 = bias[r0]; bi1 = bias[r0 + 8]; }
#pragma unroll
        for (int nt = 0; nt < 4; nt++) {
            int cc = n0 + wn * 32 + nt * 8 + 2 * tig;
            float d0 = Cf[mt][nt][0], d1 = Cf[mt][nt][1];
            float d2 = Cf[mt][nt][2], d3 = Cf[mt][nt][3];
            if (mode == 0) {
                d0 = fmaxf(d0 + bi0, 0.f); d1 = fmaxf(d1 + bi0, 0.f);
                d2 = fmaxf(d2 + bi1, 0.f); d3 = fmaxf(d3 + bi1, 0.f);
            } else if (mode == 1) {
                d0 *= scale; d1 *= scale; d2 *= scale; d3 *= scale;
            }
            *(float2*)&Cb[(long)r0 * ldc + cc]       = make_float2(d0, d1);
            *(float2*)&Cb[(long)(r0 + 8) * ldc + cc] = make_float2(d2, d3);
        }
    }
}

// ---------------------------------------------------------------------------
// Halo attention v8: 2 blocks/CTA (1024 thr), shared raw-K window,
// separable rel bias (Bh/Bw tables), tf32 mma. smem (floats):
//  KW @0      [308][68]  raw K merged window      } ST overlay [2][200][72]
//  QI @20944  [128][68]                           }
//  VJ @29648  [308][72]                           } OT overlay [2][64][68]
//  BH @51824 [14][132], BW @53672 [14][132]
//  RED @55520 [8][128], MX @56544, INV @56672 ; TOT 56800 (227,200 B)
// ---------------------------------------------------------------------------
#define A_KW  0
#define A_QI  20944
#define A_VJ  29648
#define A_BH  51824
#define A_BW  53672
#define A_RED 55520
#define A_MX  56544
#define A_INV 56672
#define A_ST  0
#define A_STB 14400
#define A_OT  29648
#define A_OTB 4352
#define A_TOT 56800

__device__ __forceinline__ int rowmap(int jl, int b) {
    if (jl >= 196) return 0;          // rows whose products are discarded/zeroed
    int iw = jl / 14;
    return iw * 22 + (jl - iw * 14) + 8 * b;
}

__global__ __launch_bounds__(1024, 1)
void attn_kernel(const float* __restrict__ gq, const float* __restrict__ gk,
                 const float* __restrict__ gv, const float* __restrict__ relh,
                 const float* __restrict__ relw, float* __restrict__ out)
{
    extern __shared__ float sm[];
    const int tid  = threadIdx.x;
    const int lane = tid & 31, w = tid >> 5;
    const int gid  = lane >> 2, tig = lane & 3;
    const int by = blockIdx.x >> 3, bp = blockIdx.x & 7;
    const int h = blockIdx.y, b = blockIdx.z;
    const int y0 = by * 8, X0 = bp * 16;
    const long qbase = (long)b * HW * 256 + h * 64;
    const long obase = ((long)b * CH + h * 64) * HW;

    // ---- phase 1: load Q (512 ent), K (1232), V (1232) ----------------------
    for (int u = tid; u < 2976; u += 1024) {
        if (u < 512) {
            int px = u >> 2, quad = u & 3;
            int bb = px >> 6, pos = px & 63;
            int p = (y0 + (pos >> 3)) * IMG + X0 + 8 * bb + (pos & 7);
            const float* src = gq + qbase + (long)p * 256 + quad * 16;
            float* dst = &sm[A_QI + px * 68 + quad * 16];
#pragma unroll
            for (int f = 0; f < 4; f++) {
                float4 v = *(const float4*)(src + f * 4);
                *(float4*)&dst[f * 4] = make_float4(tf32r(v.x), tf32r(v.y),
                                                    tf32r(v.z), tf32r(v.w));
            }
        } else {
            int e = u - 512;
            int isV = e >= 1232;
            if (isV) e -= 1232;
            int mr = e >> 2, quad = e & 3;
            int iw = mr / 22, jw2 = mr - iw * 22;
            int yw = y0 - 3 + iw, xw = X0 - 3 + jw2;
            bool valid = ((unsigned)yw < IMG) && ((unsigned)xw < IMG);
            int p = valid ? yw * IMG + xw : 0;
            const float* src = (isV ? gv : gk) + qbase + (long)p * 256 + quad * 16;
            float* dst = isV ? &sm[A_VJ + mr * 72 + quad * 16]
                             : &sm[A_KW + mr * 68 + quad * 16];
#pragma unroll
            for (int f = 0; f < 4; f++) {
                float4 v = valid ? *(const float4*)(src + f * 4)
                                 : make_float4(0.f, 0.f, 0.f, 0.f);
                *(float4*)&dst[f * 4] = make_float4(tf32r(v.x), tf32r(v.y),
                                                    tf32r(v.z), tf32r(v.w));
            }
        }
    }
    __syncthreads();

    // ---- phase 2: QK^T raw (per block) + Bh/Bw tables ------------------------
    const int b2 = w >> 4, ws = w & 15;
    const int wm = ws >> 1, wn = ws & 1;
    const int mcnt = (wm < 5) ? 2 : 1;
    const int mt0  = (wm < 5) ? 2 * wm : 10 + (wm - 5);
    float Cf[2][4][4];
#pragma unroll
    for (int mt = 0; mt < 2; mt++)
#pragma unroll
        for (int nt = 0; nt < 4; nt++)
#pragma unroll
            for (int q = 0; q < 4; q++) Cf[mt][nt][q] = 0.f;

    int r1[2], r2[2];
#pragma unroll
    for (int mt = 0; mt < 2; mt++) {
        int jl = (mt0 + mt) * 16 + gid;
        r1[mt] = rowmap(jl, b2);
        r2[mt] = rowmap(jl + 8, b2);
    }
#pragma unroll
    for (int ks = 0; ks < 8; ks++) {
        const int c0 = ks * 8;
        uint32_t Bf[4][2];
#pragma unroll
        for (int nt = 0; nt < 4; nt++) {
            int ig = b2 * 64 + wn * 32 + nt * 8 + gid;
            Bf[nt][0] = __float_as_uint(sm[A_QI + ig * 68 + c0 + tig]);
            Bf[nt][1] = __float_as_uint(sm[A_QI + ig * 68 + c0 + tig + 4]);
        }
#pragma unroll
        for (int mt = 0; mt < 2; mt++) {
            if (mt < mcnt) {
                uint32_t a0 = __float_as_uint(sm[A_KW + r1[mt] * 68 + c0 + tig]);
                uint32_t a1 = __float_as_uint(sm[A_KW + r2[mt] * 68 + c0 + tig]);
                uint32_t a2 = __float_as_uint(sm[A_KW + r1[mt] * 68 + c0 + tig + 4]);
                uint32_t a3 = __float_as_uint(sm[A_KW + r2[mt] * 68 + c0 + tig + 4]);
#pragma unroll
                for (int nt = 0; nt < 4; nt++)
                    mma8(Cf[mt][nt], a0, a1, a2, a3, Bf[nt][0], Bf[nt][1]);
            }
        }
    }
    // Bh[iw][i] = q[i,0:32]·relh[iw]; Bw[jw][i] = q[i,32:64]·relw[jw]
    for (int e = tid; e < 3584; e += 1024) {
        int isW = e >= 1792;
        int f = isW ? e - 1792 : e;
        int iw = f >> 7, ig = f & 127;
        const float* q4 = &sm[A_QI + ig * 68 + (isW ? 32 : 0)];
        const float* rl = (isW ? relw : relh) + iw * 32;
        float s = 0.f;
#pragma unroll
        for (int t = 0; t < 8; t++) {
            float4 a = *(const float4*)(q4 + t * 4);
            float4 c = *(const float4*)(rl + t * 4);
            s += a.x * c.x + a.y * c.y + a.z * c.z + a.w * c.w;
        }
        sm[(isW ? A_BW : A_BH) + iw * 132 + ig] = s;
    }
    __syncthreads();   // KW/QI dead -> ST overlay

    // ---- phase 3: store sim + bias ------------------------------------------
#pragma unroll
    for (int mt = 0; mt < 2; mt++) {
        if (mt < mcnt) {
#pragma unroll
            for (int nt = 0; nt < 4; nt++) {
                int ci = wn * 32 + nt * 8 + 2 * tig;
                int ig = b2 * 64 + ci;
#pragma unroll
                for (int hh = 0; hh < 2; hh++) {
                    int jl = (mt0 + mt) * 16 + gid + 8 * hh;
                    if (jl < 196) {
                        int iw = jl / 14, jw = jl - 14 * iw;
                        float2 bh = *(float2*)&sm[A_BH + iw * 132 + ig];
                        float2 bw = *(float2*)&sm[A_BW + jw * 132 + ig];
                        float d0 = Cf[mt][nt][2 * hh]     + bh.x + bw.x;
                        float d1 = Cf[mt][nt][2 * hh + 1] + bh.y + bw.y;
                        *(float2*)&sm[A_ST + b2 * A_STB + jl * 72 + ci] =
                            make_float2(d0, d1);
                    }
                }
            }
        }
    }
    __syncthreads();

    // ---- phase 4: softmax over j per column ig (8 j-groups) ------------------
    {
        const int ig = tid & 127, p = tid >> 7;
        const int bb = ig >> 6, i = ig & 63;
        const int cnt = (p < 4) ? 25 : 24;
        const int jb  = (p < 4) ? p * 25 : 100 + (p - 4) * 24;
        float* stb = &sm[A_ST + bb * A_STB];
        float m = -1e30f;
        for (int jj = 0; jj < cnt; jj++)
            m = fmaxf(m, stb[(jb + jj) * 72 + i]);
        sm[A_RED + p * 128 + ig] = m;
        __syncthreads();
        if (tid < 128) {
            float mm = -1e30f;
#pragma unroll
            for (int pp = 0; pp < 8; pp++)
                mm = fmaxf(mm, sm[A_RED + pp * 128 + tid]);
            sm[A_MX + tid] = mm;
        }
        __syncthreads();
        float mm = sm[A_MX + ig];
        float s = 0.f;
        for (int jj = 0; jj < cnt; jj++) {
            float e = __expf(stb[(jb + jj) * 72 + i] - mm);
            s += e;
            stb[(jb + jj) * 72 + i] = tf32r(e);
        }
        sm[A_RED + p * 128 + ig] = s;
        if (tid < 576) {   // zero ST rows 196-199 both blocks (AV k-pad)
            int zb = tid / 288, o = tid - 288 * zb;
            sm[A_ST + zb * A_STB + 196 * 72 + o] = 0.f;
        }
        __syncthreads();
        if (tid < 128) {
            float ss = 0.f;
#pragma unroll
            for (int pp = 0; pp < 8; pp++)
                ss += sm[A_RED + pp * 128 + tid];
            sm[A_INV + tid] = 1.f / ss;
        }
        __syncthreads();
    }

    // ---- phase 5: D[i][c] = attnT @ V (32 warps: 2b x 4i x 4c) ---------------
    {
        const int b3 = w >> 4, ws2 = w & 15;
        const int ibase = (ws2 >> 2) * 16;
        const int c0w = (ws2 & 3) * 16;
        float Df[2][4];
#pragma unroll
        for (int nt = 0; nt < 2; nt++)
#pragma unroll
            for (int q = 0; q < 4; q++) Df[nt][q] = 0.f;

        const float* stb = &sm[A_ST + b3 * A_STB];
        for (int kt = 0; kt < 25; kt++) {
            const int j0 = kt * 8;
            int rv1 = rowmap(j0 + tig, b3), rv2 = rowmap(j0 + tig + 4, b3);
            uint32_t a0 = __float_as_uint(stb[(j0 + tig)     * 72 + ibase + gid]);
            uint32_t a1 = __float_as_uint(stb[(j0 + tig)     * 72 + ibase + gid + 8]);
            uint32_t a2 = __float_as_uint(stb[(j0 + tig + 4) * 72 + ibase + gid]);
            uint32_t a3 = __float_as_uint(stb[(j0 + tig + 4) * 72 + ibase + gid + 8]);
#pragma unroll
            for (int nt = 0; nt < 2; nt++) {
                int c0 = c0w + nt * 8;
                uint32_t b0 = __float_as_uint(sm[A_VJ + rv1 * 72 + c0 + gid]);
                uint32_t b1 = __float_as_uint(sm[A_VJ + rv2 * 72 + c0 + gid]);
                mma8(Df[nt], a0, a1, a2, a3, b0, b1);
            }
        }
        float v0 = sm[A_INV + b3 * 64 + ibase + gid];
        float v1 = sm[A_INV + b3 * 64 + ibase + gid + 8];
        __syncthreads();   // ST/VJ dead -> OT overlay

#pragma unroll
        for (int nt = 0; nt < 2; nt++) {
            int c0 = c0w + nt * 8;
            sm[A_OT + b3 * A_OTB + (c0 + 2*tig    ) * 68 + ibase + gid]     = Df[nt][0] * v0;
            sm[A_OT + b3 * A_OTB + (c0 + 2*tig + 1) * 68 + ibase + gid]     = Df[nt][1] * v0;
            sm[A_OT + b3 * A_OTB + (c0 + 2*tig    ) * 68 + ibase + gid + 8] = Df[nt][2] * v1;
            sm[A_OT + b3 * A_OTB + (c0 + 2*tig + 1) * 68 + ibase + gid + 8] = Df[nt][3] * v1;
        }
        __syncthreads();

        int bb = tid >> 9, c = (tid >> 3) & 63, r = tid & 7;
        float4 o0 = *(const float4*)&sm[A_OT + bb * A_OTB + c * 68 + r * 8];
        float4 o1 = *(const float4*)&sm[A_OT + bb * A_OTB + c * 68 + r * 8 + 4];
        float* dst = out + obase + (long)c * HW + (y0 + r) * IMG + X0 + 8 * bb;
        *(float4*)&dst[0] = o0;
        *(float4*)&dst[4] = o1;
    }
}

// ---------------------------------------------------------------------------
extern "C" void kernel_launch(void* const* d_in, const int* in_sizes, int n_in,
                              void* d_out, int out_size)
{
    const float* noisy = (const float*)d_in[0];
    const float* aux   = (const float*)d_in[1];
    const float* w_map = (const float*)d_in[2];
    const float* b_map = (const float*)d_in[3];
    const float* w_q   = (const float*)d_in[4];
    const float* w_k   = (const float*)d_in[5];
    const float* w_v   = (const float*)d_in[6];
    const float* rel_h = (const float*)d_in[7];
    const float* rel_w = (const float*)d_in[8];
    float* out = (float*)d_out;

    float *naux, *q, *k, *v, *wt;
    cudaGetSymbolAddress((void**)&naux, g_naux);
    cudaGetSymbolAddress((void**)&q,    g_q);
    cudaGetSymbolAddress((void**)&k,    g_k);
    cudaGetSymbolAddress((void**)&v,    g_v);
    cudaGetSymbolAddress((void**)&wt,   g_wt);

    transpose_w<<<1280, 256>>>(w_map, w_q, w_k, w_v, wt);

    const long XB = (long)CH * HW;
    dim3 ggrid(128, 2, BATCH);
    gemm_b<<<ggrid, 256>>>(wt, 0, 256, noisy, aux, XB, HW, 512, 256,
                           naux, HW, b_map, 1.f, 0, 0);
    gemm_b<<<ggrid, 256>>>(naux,  XB, HW, wt + 131072, nullptr, 0, 256, 256, 256,
                           q, 256, nullptr, 0.125f, 1, 1);
    gemm_b<<<ggrid, 256>>>(naux,  XB, HW, wt + 196608, nullptr, 0, 256, 256, 256,
                           k, 256, nullptr, 1.f, 2, 1);
    gemm_b<<<ggrid, 256>>>(noisy, XB, HW, wt + 262144, nullptr, 0, 256, 256, 256,
                           v, 256, nullptr, 1.f, 2, 1);

    size_t smem = (size_t)A_TOT * sizeof(float);   // 227,200 B
    cudaFuncSetAttribute(attn_kernel,
                         cudaFuncAttributeMaxDynamicSharedMemorySize, (int)smem);
    attn_kernel<<<dim3(128, HEADS, BATCH), 1024, smem>>>(q, k, v, rel_h, rel_w, out);
}

// round 14
// speedup vs baseline: 1.1599x; 1.1599x over previous
#include <cuda_runtime.h>
#include <cstdint>

#define CH   256
#define IMG  128
#define HW   (IMG*IMG)
#define BATCH 4
#define HEADS 4
#define NB   16
#define BLK  8
#define HALO 3

__device__ __forceinline__ float tf32r(float x) {
    uint32_t r; asm("cvt.rna.tf32.f32 %0, %1;" : "=r"(r) : "f"(x));
    return __uint_as_float(r);
}
__device__ __forceinline__ void mma8(float* d, uint32_t a0, uint32_t a1,
                                     uint32_t a2, uint32_t a3,
                                     uint32_t b0, uint32_t b1) {
    asm("mma.sync.aligned.m16n8k8.row.col.f32.tf32.tf32.f32 "
        "{%0,%1,%2,%3},{%4,%5,%6,%7},{%8,%9},{%0,%1,%2,%3};"
        : "+f"(d[0]), "+f"(d[1]), "+f"(d[2]), "+f"(d[3])
        : "r"(a0), "r"(a1), "r"(a2), "r"(a3), "r"(b0), "r"(b1));
}
__device__ __forceinline__ void mma16b(float* d, const uint32_t* a,
                                       uint32_t b0, uint32_t b1) {
    asm("mma.sync.aligned.m16n8k16.row.col.f32.bf16.bf16.f32 "
        "{%0,%1,%2,%3},{%4,%5,%6,%7},{%8,%9},{%0,%1,%2,%3};"
        : "+f"(d[0]), "+f"(d[1]), "+f"(d[2]), "+f"(d[3])
        : "r"(a[0]), "r"(a[1]), "r"(a[2]), "r"(a[3]), "r"(b0), "r"(b1));
}
__device__ __forceinline__ void bsplit2(float xe, float xo,
                                        uint32_t& hi, uint32_t& lo) {
    uint32_t h;
    asm("cvt.rn.bf16x2.f32 %0, %1, %2;" : "=r"(h) : "f"(xo), "f"(xe));
    float re = xe - __uint_as_float(h << 16);
    float ro = xo - __uint_as_float(h & 0xffff0000u);
    asm("cvt.rn.bf16x2.f32 %0, %1, %2;" : "=r"(lo) : "f"(ro), "f"(re));
    hi = h;
}

__device__ float g_naux[(long)BATCH*CH*HW];
__device__ float g_q   [(long)BATCH*HW*CH];
__device__ float g_k   [(long)BATCH*HW*CH];
__device__ float g_v   [(long)BATCH*HW*CH];
__device__ float g_wt  [512*256 + 3*256*256];

__global__ void transpose_w(const float* __restrict__ wm,
                            const float* __restrict__ wq,
                            const float* __restrict__ wk,
                            const float* __restrict__ wv,
                            float* __restrict__ wt)
{
    int t = blockIdx.x * 256 + threadIdx.x;
    if (t < 131072)      { int k = t >> 8, o = t & 255; wt[t] = wm[o * 512 + k]; }
    else if (t < 196608) { int u = t - 131072; wt[t] = wq[(u & 255) * 256 + (u >> 8)]; }
    else if (t < 262144) { int u = t - 196608; wt[t] = wk[(u & 255) * 256 + (u >> 8)]; }
    else if (t < 327680) { int u = t - 262144; wt[t] = wv[(u & 255) * 256 + (u >> 8)]; }
}

// ---------------------------------------------------------------------------
// Split-bf16 tensor-core conv GEMM — R12 + single-sync mainloop.
// ---------------------------------------------------------------------------
__global__ __launch_bounds__(256, 2)
void gemm_b(const float* __restrict__ P,  long pB, int ldP,
            const float* __restrict__ Q0, const float* __restrict__ Q1,
            long qB, int ldQ, int K, int K0,
            float* __restrict__ C, int ldc,
            const float* __restrict__ bias, float scale, int mode, int mswap)
{
    const int tid  = threadIdx.x;
    const int lane = tid & 31, w = tid >> 5;
    const int gid  = lane >> 2, tig = lane & 3;
    const int b    = blockIdx.z;
    const int m0   = (mswap ? blockIdx.x : blockIdx.y) * 128;
    const int n0   = (mswap ? blockIdx.y : blockIdx.x) * 128;
    const float* Pb  = P  + (long)b * pB;
    const float* Q0b = Q0 + (long)b * qB;
    const float* Q1b = Q1 ? (Q1 + (long)b * qB) : nullptr;
    float* Cb = C + (long)b * CH * HW;

    __shared__ uint32_t PH[2][8][136], PL[2][8][136];
    __shared__ uint32_t QH[2][8][136], QL[2][8][136];

    const int side = tid >> 7;
    const int lt   = tid & 127;
    const int k2   = lt >> 4;
    const int mq   = (lt & 15) * 8;

    const int wm = w >> 2, wn = w & 3;
    float Cf[4][4][4];
#pragma unroll
    for (int mt = 0; mt < 4; mt++)
#pragma unroll
        for (int nt = 0; nt < 4; nt++)
#pragma unroll
            for (int q = 0; q < 4; q++) Cf[mt][nt][q] = 0.f;

    const int ntiles = K / 16;
    float4 e0, e1, o0, o1;

    auto loadT = [&](int kb) {
        int kr = kb + 2 * k2;
        if (side == 0) {
            const float* s0 = Pb + (long)kr * ldP + m0 + mq;
            const float* s1 = s0 + ldP;
            e0 = *(const float4*)&s0[0]; e1 = *(const float4*)&s0[4];
            o0 = *(const float4*)&s1[0]; o1 = *(const float4*)&s1[4];
        } else {
            const float* s0 = ((kr     < K0) ? (Q0b + (long)kr * ldQ)
                                             : (Q1b + (long)(kr - K0) * ldQ)) + n0 + mq;
            const float* s1 = ((kr + 1 < K0) ? (Q0b + (long)(kr + 1) * ldQ)
                                             : (Q1b + (long)(kr + 1 - K0) * ldQ)) + n0 + mq;
            e0 = *(const float4*)&s0[0]; e1 = *(const float4*)&s0[4];
            o0 = *(const float4*)&s1[0]; o1 = *(const float4*)&s1[4];
        }
    };
    auto storeT = [&](int buf) {
        float ev[8] = {e0.x,e0.y,e0.z,e0.w,e1.x,e1.y,e1.z,e1.w};
        float ov[8] = {o0.x,o0.y,o0.z,o0.w,o1.x,o1.y,o1.z,o1.w};
        uint32_t hs[8], ls[8];
#pragma unroll
        for (int m = 0; m < 8; m++) bsplit2(ev[m], ov[m], hs[m], ls[m]);
        uint32_t* H = side ? &QH[buf][k2][mq] : &PH[buf][k2][mq];
        uint32_t* L = side ? &QL[buf][k2][mq] : &PL[buf][k2][mq];
        *(uint4*)&H[0] = make_uint4(hs[0], hs[1], hs[2], hs[3]);
        *(uint4*)&H[4] = make_uint4(hs[4], hs[5], hs[6], hs[7]);
        *(uint4*)&L[0] = make_uint4(ls[0], ls[1], ls[2], ls[3]);
        *(uint4*)&L[4] = make_uint4(ls[4], ls[5], ls[6], ls[7]);
    };

    loadT(0); storeT(0);
    __syncthreads();

    for (int kt = 0; kt < ntiles; kt++) {
        const int cur = kt & 1, nxt = cur ^ 1;
        if (kt + 1 < ntiles) loadT((kt + 1) * 16);

        uint32_t bh[4][2], bl[4][2];
#pragma unroll
        for (int nt = 0; nt < 4; nt++) {
            int n = wn * 32 + nt * 8 + gid;
            bh[nt][0] = QH[cur][tig][n];     bh[nt][1] = QH[cur][tig + 4][n];
            bl[nt][0] = QL[cur][tig][n];     bl[nt][1] = QL[cur][tig + 4][n];
        }
#pragma unroll
        for (int mt = 0; mt < 4; mt++) {
            int m = wm * 64 + mt * 16 + gid;
            uint32_t ah[4] = {PH[cur][tig][m], PH[cur][tig][m + 8],
                              PH[cur][tig + 4][m], PH[cur][tig + 4][m + 8]};
            uint32_t al[4] = {PL[cur][tig][m], PL[cur][tig][m + 8],
                              PL[cur][tig + 4][m], PL[cur][tig + 4][m + 8]};
#pragma unroll
            for (int nt = 0; nt < 4; nt++) {
                mma16b(Cf[mt][nt], ah, bh[nt][0], bh[nt][1]);
                mma16b(Cf[mt][nt], ah, bl[nt][0], bl[nt][1]);
                mma16b(Cf[mt][nt], al, bh[nt][0], bh[nt][1]);
            }
        }
        if (kt + 1 < ntiles) { storeT(nxt); __syncthreads(); }
    }

#pragma unroll
    for (int mt = 0; mt < 4; mt++) {
        int r0 = m0 + wm * 64 + mt * 16 + gid;
        float bi0 = 0.f, bi1 = 0.f;
        if (mode == 0) { bi0 = bias[r0]; bi1 = bias[r0 + 8]; }
#pragma unroll
        for (int nt = 0; nt < 4; nt++) {
            int cc = n0 + wn * 32 + nt * 8 + 2 * tig;
            float d0 = Cf[mt][nt][0], d1 = Cf[mt][nt][1];
            float d2 = Cf[mt][nt][2], d3 = Cf[mt][nt][3];
            if (mode == 0) {
                d0 = fmaxf(d0 + bi0, 0.f); d1 = fmaxf(d1 + bi0, 0.f);
                d2 = fmaxf(d2 + bi1, 0.f); d3 = fmaxf(d3 + bi1, 0.f);
            } else if (mode == 1) {
                d0 *= scale; d1 *= scale; d2 *= scale; d3 *= scale;
            }
            *(float2*)&Cb[(long)r0 * ldc + cc]       = make_float2(d0, d1);
            *(float2*)&Cb[(long)(r0 + 8) * ldc + cc] = make_float2(d2, d3);
        }
    }
}

// ---------------------------------------------------------------------------
// Halo attention — R12 structure; QK^T warp grid rebalanced 8m x 2n.
// ---------------------------------------------------------------------------
#define KW_OFF 0
#define KW_STR 68
#define QI_OFF 13600
#define QI_STR 68
#define ST_OFF 0
#define ST_STR 72
#define VJ_OFF 17952
#define VJ_STR 72
#define OT_OFF 0
#define OT_STR 68
#define RED_OFF 32352
#define MX_OFF 32864
#define INV_OFF 32928
#define SM_TOT 32992

__global__ __launch_bounds__(512, 1)
void attn_kernel(const float* __restrict__ gq, const float* __restrict__ gk,
                 const float* __restrict__ gv, const float* __restrict__ relh,
                 const float* __restrict__ relw, float* __restrict__ out)
{
    extern __shared__ float sm[];
    const int tid  = threadIdx.x;
    const int lane = tid & 31, w = tid >> 5;
    const int gid  = lane >> 2, tig = lane & 3;
    const int by = blockIdx.x >> 4, bx = blockIdx.x & 15;
    const int h = blockIdx.y, b = blockIdx.z;
    const int y0 = by * BLK, x0 = bx * BLK;
    const long qbase = (long)b * HW * 256 + h * 64;
    const long obase = ((long)b * CH + h * 64) * HW;

    if (tid < 272)      sm[KW_OFF + 196 * KW_STR + tid] = 0.f;
    else if (tid < 560) sm[VJ_OFF + 196 * VJ_STR + (tid - 272)] = 0.f;

    if (tid < 256) {
        int px = tid >> 2, quad = tid & 3;
        int p = (y0 + (px >> 3)) * IMG + x0 + (px & 7);
        const float* src = gq + qbase + (long)p * 256 + quad * 16;
        float* dst = &sm[QI_OFF + px * QI_STR + quad * 16];
#pragma unroll
        for (int f = 0; f < 4; f++) {
            float4 v = *(const float4*)(src + f * 4);
            *(float4*)&dst[f * 4] = make_float4(tf32r(v.x), tf32r(v.y),
                                                tf32r(v.z), tf32r(v.w));
        }
    }
    for (int u = tid; u < 1568; u += 512) {
        int isV = u >= 784;
        int e = isV ? u - 784 : u;
        int j = e >> 2, quad = e & 3;
        int iw = j / 14, jw = j - iw * 14;
        int yw = y0 - HALO + iw, xw = x0 - HALO + jw;
        bool valid = ((unsigned)yw < IMG) && ((unsigned)xw < IMG);
        int p = valid ? (yw * IMG + xw) : 0;
        if (!isV) {
            const float* src  = gk + qbase + (long)p * 256 + quad * 16;
            const float* bsrc = (quad < 2) ? (relh + iw * 32 + quad * 16)
                                           : (relw + jw * 32 + (quad - 2) * 16);
            float* dst = &sm[KW_OFF + j * KW_STR + quad * 16];
#pragma unroll
            for (int f = 0; f < 4; f++) {
                float4 bv = *(const float4*)(bsrc + f * 4);
                float4 kv = valid ? *(const float4*)(src + f * 4)
                                  : make_float4(0.f, 0.f, 0.f, 0.f);
                *(float4*)&dst[f * 4] =
                    make_float4(tf32r(kv.x + bv.x), tf32r(kv.y + bv.y),
                                tf32r(kv.z + bv.z), tf32r(kv.w + bv.w));
            }
        } else {
            const float* src = gv + qbase + (long)p * 256 + quad * 16;
            float* dst = &sm[VJ_OFF + j * VJ_STR + quad * 16];
#pragma unroll
            for (int f = 0; f < 4; f++) {
                float4 kv = valid ? *(const float4*)(src + f * 4)
                                  : make_float4(0.f, 0.f, 0.f, 0.f);
                *(float4*)&dst[f * 4] = make_float4(tf32r(kv.x), tf32r(kv.y),
                                                    tf32r(kv.z), tf32r(kv.w));
            }
        }
    }
    __syncthreads();

    // ---- QK^T: 16 warps = 8 m-groups x 2 n-groups (4 n8-tiles each) ---------
    const int wm = w >> 1, wn = w & 1;
    const int mcnt   = (wm < 5) ? 2 : 1;
    const int mtile0 = (wm < 5) ? 2 * wm : 10 + (wm - 5);
    float Cf[2][4][4];
#pragma unroll
    for (int mt = 0; mt < 2; mt++)
#pragma unroll
        for (int nt = 0; nt < 4; nt++)
#pragma unroll
            for (int q = 0; q < 4; q++) Cf[mt][nt][q] = 0.f;

#pragma unroll
    for (int ks = 0; ks < 8; ks++) {
        const int c0 = ks * 8;
        uint32_t Bf[4][2];
#pragma unroll
        for (int nt = 0; nt < 4; nt++) {
            int n = wn * 32 + nt * 8 + gid;
            Bf[nt][0] = __float_as_uint(sm[QI_OFF + n * QI_STR + c0 + tig]);
            Bf[nt][1] = __float_as_uint(sm[QI_OFF + n * QI_STR + c0 + tig + 4]);
        }
#pragma unroll
        for (int mt = 0; mt < 2; mt++) {
            if (mt < mcnt) {
                int r = (mtile0 + mt) * 16 + gid;
                uint32_t a0 = __float_as_uint(sm[KW_OFF + r       * KW_STR + c0 + tig]);
                uint32_t a1 = __float_as_uint(sm[KW_OFF + (r + 8) * KW_STR + c0 + tig]);
                uint32_t a2 = __float_as_uint(sm[KW_OFF + r       * KW_STR + c0 + tig + 4]);
                uint32_t a3 = __float_as_uint(sm[KW_OFF + (r + 8) * KW_STR + c0 + tig + 4]);
#pragma unroll
                for (int nt = 0; nt < 4; nt++)
                    mma8(Cf[mt][nt], a0, a1, a2, a3, Bf[nt][0], Bf[nt][1]);
            }
        }
    }
    __syncthreads();   // KW/QI dead -> simT overlay

#pragma unroll
    for (int mt = 0; mt < 2; mt++) {
        if (mt < mcnt) {
#pragma unroll
            for (int nt = 0; nt < 4; nt++) {
                int r = (mtile0 + mt) * 16 + gid;
                int ci = wn * 32 + nt * 8 + 2 * tig;
                *(float2*)&sm[ST_OFF + r * ST_STR + ci] =
                    make_float2(Cf[mt][nt][0], Cf[mt][nt][1]);
                if (r + 8 < 200)
                    *(float2*)&sm[ST_OFF + (r + 8) * ST_STR + ci] =
                        make_float2(Cf[mt][nt][2], Cf[mt][nt][3]);
            }
        }
    }
    __syncthreads();

    {
        const int i = tid & 63, p = tid >> 6;
        const int cnt = (p < 4) ? 25 : 24;
        const int jb  = (p < 4) ? p * 25 : 100 + (p - 4) * 24;
        float m = -1e30f;
        for (int jj = 0; jj < cnt; jj++)
            m = fmaxf(m, sm[ST_OFF + (jb + jj) * ST_STR + i]);
        sm[RED_OFF + p * 64 + i] = m;
        __syncthreads();
        if (tid < 64) {
            float mm = -1e30f;
#pragma unroll
            for (int pp = 0; pp < 8; pp++)
                mm = fmaxf(mm, sm[RED_OFF + pp * 64 + tid]);
            sm[MX_OFF + tid] = mm;
        }
        __syncthreads();
        float mm = sm[MX_OFF + i];
        float s = 0.f;
        for (int jj = 0; jj < cnt; jj++) {
            float e = __expf(sm[ST_OFF + (jb + jj) * ST_STR + i] - mm);
            s += e;
            sm[ST_OFF + (jb + jj) * ST_STR + i] = tf32r(e);
        }
        sm[RED_OFF + p * 64 + i] = s;
        if (tid < 4 * ST_STR) sm[ST_OFF + 196 * ST_STR + tid] = 0.f;
        __syncthreads();
        if (tid < 64) {
            float ss = 0.f;
#pragma unroll
            for (int pp = 0; pp < 8; pp++)
                ss += sm[RED_OFF + pp * 64 + tid];
            sm[INV_OFF + tid] = 1.f / ss;
        }
        __syncthreads();
    }

    {
        const int ibase = (w >> 2) * 16;
        const int wn2 = w & 3;
        float Df[2][4];
#pragma unroll
        for (int nt = 0; nt < 2; nt++)
#pragma unroll
            for (int q = 0; q < 4; q++) Df[nt][q] = 0.f;

        for (int kt = 0; kt < 25; kt++) {
            const int j0 = kt * 8;
            uint32_t a0 = __float_as_uint(sm[ST_OFF + (j0 + tig)     * ST_STR + ibase + gid]);
            uint32_t a1 = __float_as_uint(sm[ST_OFF + (j0 + tig)     * ST_STR + ibase + gid + 8]);
            uint32_t a2 = __float_as_uint(sm[ST_OFF + (j0 + tig + 4) * ST_STR + ibase + gid]);
            uint32_t a3 = __float_as_uint(sm[ST_OFF + (j0 + tig + 4) * ST_STR + ibase + gid + 8]);
#pragma unroll
            for (int nt = 0; nt < 2; nt++) {
                int c0 = wn2 * 16 + nt * 8;
                uint32_t b0 = __float_as_uint(sm[VJ_OFF + (j0 + tig)     * VJ_STR + c0 + gid]);
                uint32_t b1 = __float_as_uint(sm[VJ_OFF + (j0 + tig + 4) * VJ_STR + c0 + gid]);
                mma8(Df[nt], a0, a1, a2, a3, b0, b1);
            }
        }
        float v0 = sm[INV_OFF + ibase + gid];
        float v1 = sm[INV_OFF + ibase + gid + 8];
        __syncthreads();

#pragma unroll
        for (int nt = 0; nt < 2; nt++) {
            int c0 = wn2 * 16 + nt * 8;
            sm[OT_OFF + (c0 + 2*tig    ) * OT_STR + ibase + gid]     = Df[nt][0] * v0;
            sm[OT_OFF + (c0 + 2*tig + 1) * OT_STR + ibase + gid]     = Df[nt][1] * v0;
            sm[OT_OFF + (c0 + 2*tig    ) * OT_STR + ibase + gid + 8] = Df[nt][2] * v1;
            sm[OT_OFF + (c0 + 2*tig + 1) * OT_STR + ibase + gid + 8] = Df[nt][3] * v1;
        }
        __syncthreads();

        int c = tid >> 3, r = tid & 7;
        float4 o0 = *(const float4*)&sm[OT_OFF + c * OT_STR + r * 8];
        float4 o1 = *(const float4*)&sm[OT_OFF + c * OT_STR + r * 8 + 4];
        float* dst = out + obase + (long)c * HW + (y0 + r) * IMG + x0;
        *(float4*)&dst[0] = o0;
        *(float4*)&dst[4] = o1;
    }
}

// ---------------------------------------------------------------------------
extern "C" void kernel_launch(void* const* d_in, const int* in_sizes, int n_in,
                              void* d_out, int out_size)
{
    const float* noisy = (const float*)d_in[0];
    const float* aux   = (const float*)d_in[1];
    const float* w_map = (const float*)d_in[2];
    const float* b_map = (const float*)d_in[3];
    const float* w_q   = (const float*)d_in[4];
    const float* w_k   = (const float*)d_in[5];
    const float* w_v   = (const float*)d_in[6];
    const float* rel_h = (const float*)d_in[7];
    const float* rel_w = (const float*)d_in[8];
    float* out = (float*)d_out;

    float *naux, *q, *k, *v, *wt;
    cudaGetSymbolAddress((void**)&naux, g_naux);
    cudaGetSymbolAddress((void**)&q,    g_q);
    cudaGetSymbolAddress((void**)&k,    g_k);
    cudaGetSymbolAddress((void**)&v,    g_v);
    cudaGetSymbolAddress((void**)&wt,   g_wt);

    transpose_w<<<1280, 256>>>(w_map, w_q, w_k, w_v, wt);

    const long XB = (long)CH * HW;
    dim3 ggrid(128, 2, BATCH);
    gemm_b<<<ggrid, 256>>>(wt, 0, 256, noisy, aux, XB, HW, 512, 256,
                           naux, HW, b_map, 1.f, 0, 0);
    gemm_b<<<ggrid, 256>>>(naux,  XB, HW, wt + 131072, nullptr, 0, 256, 256, 256,
                           q, 256, nullptr, 0.125f, 1, 1);
    gemm_b<<<ggrid, 256>>>(naux,  XB, HW, wt + 196608, nullptr, 0, 256, 256, 256,
                           k, 256, nullptr, 1.f, 2, 1);
    gemm_b<<<ggrid, 256>>>(noisy, XB, HW, wt + 262144, nullptr, 0, 256, 256, 256,
                           v, 256, nullptr, 1.f, 2, 1);

    size_t smem = (size_t)SM_TOT * sizeof(float);
    cudaFuncSetAttribute(attn_kernel,
                         cudaFuncAttributeMaxDynamicSharedMemorySize, (int)smem);
    attn_kernel<<<dim3(NB * NB, HEADS, BATCH), 512, smem>>>(q, k, v, rel_h, rel_w, out);
}